// round 12
// baseline (speedup 1.0000x reference)
#include <cuda_runtime.h>
#include <math.h>
#include <float.h>
#include <stdint.h>

#define BB 64
#define SS 2048
#define ED 1024
#define AD 512

// Scratch (allocation-free rule: __device__ globals)
__device__ float g_dec_feat[BB * AD];       // [B, AD]
__device__ float g_part[4 * BB * SS];       // [nc][B, S] score partials
__device__ int   g_mask_mode;               // 0=int32, 1=float32, 2=uint8

__device__ __forceinline__ uint32_t smem_u32(const void* p) {
    uint32_t a;
    asm("{ .reg .u64 t; cvta.to.shared.u64 t, %1; cvt.u32.u64 %0, t; }"
        : "=r"(a) : "l"(p));
    return a;
}
__device__ __forceinline__ uint32_t f2tf32(float x) {
    uint32_t r;
    asm("cvt.rna.tf32.f32 %0, %1;" : "=r"(r) : "f"(x));
    return r;
}
__device__ __forceinline__ void mbar_init(uint32_t addr, uint32_t cnt) {
    asm volatile("mbarrier.init.shared.b64 [%0], %1;" :: "r"(addr), "r"(cnt) : "memory");
}
// acquire wait (orders subsequent generic LDS reads after async-proxy writes)
__device__ __forceinline__ void mbar_wait_acq(uint32_t addr, uint32_t parity) {
    uint32_t done;
    asm volatile(
        "{ .reg .pred p; mbarrier.try_wait.parity.acquire.cta.shared::cta.b64 p, [%1], %2; selp.b32 %0,1,0,p; }"
        : "=r"(done) : "r"(addr), "r"(parity) : "memory");
    if (!done) {
        asm volatile(
            "{ .reg .pred P1; WL%=: mbarrier.try_wait.parity.acquire.cta.shared::cta.b64 P1, [%0], %1, 0x989680; @P1 bra.uni WD%=; bra.uni WL%=; WD%=: }"
            :: "r"(addr), "r"(parity) : "memory");
    }
}
__device__ __forceinline__ void mbar_expect_tx(uint32_t addr, uint32_t bytes) {
    asm volatile("mbarrier.arrive.expect_tx.shared.b64 _, [%0], %1;"
                 :: "r"(addr), "r"(bytes) : "memory");
}
__device__ __forceinline__ void bulk_g2s(uint32_t dst, const void* src,
                                         uint32_t bytes, uint32_t mbar) {
    asm volatile(
        "cp.async.bulk.shared::cluster.global.mbarrier::complete_tx::bytes [%0], [%1], %2, [%3];"
        :: "r"(dst), "l"(src), "r"(bytes), "r"(mbar) : "memory");
}
// fast tanh via exp (rel err ~1e-6)
__device__ __forceinline__ float fast_tanh(float v) {
    v = fminf(fmaxf(v, -12.f), 12.f);
    float e = __expf(2.f * v);
    return __fdividef(e - 1.f, e + 1.f);
}

// ---------------------------------------------------------------------------
// Kernel 1: dec_feat[b][a] = dot(decoder_hidden[b], W_dec[a])
// ---------------------------------------------------------------------------
__global__ void decfeat_kernel(const float* __restrict__ dh,
                               const float* __restrict__ Wdec) {
    int b = blockIdx.x;
    __shared__ float s_dh[ED];
    for (int i = threadIdx.x; i < ED; i += 256) s_dh[i] = dh[b * ED + i];
    __syncthreads();
    int warp = threadIdx.x >> 5;
    int lane = threadIdx.x & 31;
    int a = blockIdx.y * 8 + warp;
    const float* wr = Wdec + (size_t)a * ED;
    float acc = 0.f;
    #pragma unroll 8
    for (int k = lane; k < ED; k += 32) acc += s_dh[k] * wr[k];
    #pragma unroll
    for (int off = 16; off; off >>= 1) acc += __shfl_down_sync(0xffffffffu, acc, off);
    if (lane == 0) g_dec_feat[b * AD + a] = acc;
}

// ---------------------------------------------------------------------------
// Kernel 2: tf32 mma.sync fused score kernel, cp.async.bulk loads.
// Per CTA: 128 s-rows x 128 a-cols, K=1024, BK=32, 4-stage bulk+mbar pipeline.
// partial[nc][b,s] = sum_{a in chunk} We[a] * tanh(X.Wenc^T + dec)
// ---------------------------------------------------------------------------
#define BK 32
#define NK (ED / BK)          // 32
#define NSTAGE 4
#define RS 36                 // smem row stride in floats (36 % 32 == 4), 144B (16B mult)
#define STAGE_FLOATS (256 * RS)   // X 128 rows + W 128 rows
#define ROW_BYTES 128u            // BK floats
#define STAGE_TX (256u * ROW_BYTES)  // 32KB per stage

__global__ void __launch_bounds__(256, 1)
score_mma_kernel(const float* __restrict__ X,     // [B*S, ED]
                 const float* __restrict__ Wenc,  // [AD, ED]
                 const float* __restrict__ Wen)   // [AD]
{
    extern __shared__ float smem[];
    __shared__ uint64_t s_mb[NSTAGE];
    __shared__ float s_dec[128];
    __shared__ float s_we[128];
    __shared__ float s_red[2][128];

    int tid  = threadIdx.x;
    int wid  = tid >> 5;
    int lane = tid & 31;
    int g    = lane >> 2;
    int tig  = lane & 3;
    int warpm = wid & 3;       // 0..3
    int warpn = wid >> 2;      // 0..1

    int nc = blockIdx.x & 3;
    int b  = blockIdx.x >> 2;
    int s0 = blockIdx.y * 128;

    const float* Xblk = X + (size_t)(b * SS + s0) * ED;
    const float* Wblk = Wenc + (size_t)(nc * 128) * ED;

    for (int i = tid; i < 128; i += 256) {
        s_dec[i] = g_dec_feat[b * AD + nc * 128 + i];
        s_we[i]  = Wen[nc * 128 + i];
    }

    uint32_t sm0 = smem_u32(smem);
    uint32_t mb[NSTAGE];
    #pragma unroll
    for (int i = 0; i < NSTAGE; ++i) mb[i] = smem_u32(&s_mb[i]);

    if (tid == 0) {
        #pragma unroll
        for (int i = 0; i < NSTAGE; ++i) mbar_init(mb[i], 256);
    }
    __syncthreads();

    // each thread owns one 128B row per stage: tid<128 -> X row tid,
    // tid>=128 -> W row (tid-128). dst offset = tid*RS floats.
    const float* mysrc_base = (tid < 128)
        ? Xblk + (size_t)tid * ED
        : Wblk + (size_t)(tid - 128) * ED;
    uint32_t mydst_off = (uint32_t)(tid * RS) * 4u;

    auto issue_stage = [&](int p, int kc) {
        uint32_t m = mb[p];
        mbar_expect_tx(m, ROW_BYTES);
        bulk_g2s(sm0 + (uint32_t)(p * STAGE_FLOATS) * 4u + mydst_off,
                 mysrc_base + kc * BK, ROW_BYTES, m);
    };

    // prologue: stages 0..2
    issue_stage(0, 0);
    issue_stage(1, 1);
    issue_stage(2, 2);

    float acc[2][8][4];
    #pragma unroll
    for (int mf = 0; mf < 2; ++mf)
        #pragma unroll
        for (int nf = 0; nf < 8; ++nf)
            #pragma unroll
            for (int r = 0; r < 4; ++r) acc[mf][nf][r] = 0.f;

    int ph[NSTAGE] = {0, 0, 0, 0};

    for (int kt = 0; kt < NK; ++kt) {
        int p = kt & (NSTAGE - 1);
        mbar_wait_acq(mb[p], (uint32_t)ph[p]);
        ph[p] ^= 1;
        __syncthreads();   // all warps done with stage (kt-1)&3 -> safe to refill

        if (kt + NSTAGE - 1 < NK)
            issue_stage((kt + NSTAGE - 1) & (NSTAGE - 1), kt + NSTAGE - 1);

        const float* xs = smem + p * STAGE_FLOATS;
        const float* ws = xs + 128 * RS;

        #pragma unroll
        for (int ks = 0; ks < 4; ++ks) {
            int kb = ks * 8 + tig;
            uint32_t A[2][4];
            #pragma unroll
            for (int mf = 0; mf < 2; ++mf) {
                int r = warpm * 32 + mf * 16 + g;
                const float* xr = xs + r * RS + kb;
                A[mf][0] = f2tf32(xr[0]);
                A[mf][1] = f2tf32(xr[8 * RS]);
                A[mf][2] = f2tf32(xr[4]);
                A[mf][3] = f2tf32(xr[8 * RS + 4]);
            }
            uint32_t Bf[8][2];
            #pragma unroll
            for (int nf = 0; nf < 8; ++nf) {
                int n = warpn * 64 + nf * 8 + g;
                const float* wr = ws + n * RS + kb;
                Bf[nf][0] = f2tf32(wr[0]);
                Bf[nf][1] = f2tf32(wr[4]);
            }
            #pragma unroll
            for (int mf = 0; mf < 2; ++mf)
                #pragma unroll
                for (int nf = 0; nf < 8; ++nf) {
                    float* c = acc[mf][nf];
                    asm volatile(
                        "mma.sync.aligned.m16n8k8.row.col.f32.tf32.tf32.f32 "
                        "{%0,%1,%2,%3}, {%4,%5,%6,%7}, {%8,%9}, {%0,%1,%2,%3};"
                        : "+f"(c[0]), "+f"(c[1]), "+f"(c[2]), "+f"(c[3])
                        : "r"(A[mf][0]), "r"(A[mf][1]), "r"(A[mf][2]), "r"(A[mf][3]),
                          "r"(Bf[nf][0]), "r"(Bf[nf][1]));
                }
        }
        __syncthreads();   // all warps done reading stage p before next refill
    }

    // ---- epilogue: tanh + We reduction ----
    #pragma unroll
    for (int mf = 0; mf < 2; ++mf) {
        float sum0 = 0.f, sum1 = 0.f;
        #pragma unroll
        for (int nf = 0; nf < 8; ++nf) {
            int cA = warpn * 64 + nf * 8 + 2 * tig;
            int cB = cA + 1;
            sum0 += s_we[cA] * fast_tanh(acc[mf][nf][0] + s_dec[cA])
                  + s_we[cB] * fast_tanh(acc[mf][nf][1] + s_dec[cB]);
            sum1 += s_we[cA] * fast_tanh(acc[mf][nf][2] + s_dec[cA])
                  + s_we[cB] * fast_tanh(acc[mf][nf][3] + s_dec[cB]);
        }
        sum0 += __shfl_xor_sync(0xffffffffu, sum0, 1);
        sum0 += __shfl_xor_sync(0xffffffffu, sum0, 2);
        sum1 += __shfl_xor_sync(0xffffffffu, sum1, 1);
        sum1 += __shfl_xor_sync(0xffffffffu, sum1, 2);
        if (tig == 0) {
            int r0 = warpm * 32 + mf * 16 + g;
            s_red[warpn][r0]     = sum0;
            s_red[warpn][r0 + 8] = sum1;
        }
    }
    __syncthreads();
    if (tid < 128)
        g_part[nc * BB * SS + b * SS + s0 + tid] = s_red[0][tid] + s_red[1][tid];
}

// ---------------------------------------------------------------------------
// Kernel 3: mask dtype detect
// ---------------------------------------------------------------------------
__global__ void mask_detect_kernel(const unsigned int* __restrict__ mw) {
    __shared__ int s_not01, s_notf;
    if (threadIdx.x == 0) { s_not01 = 0; s_notf = 0; }
    __syncthreads();
    int not01 = 0, notf = 0;
    for (int i = threadIdx.x; i < 32768; i += blockDim.x) {
        unsigned int w = mw[i];
        if (w > 1u) not01 = 1;
        if (w != 0u && w != 0x3F800000u) notf = 1;
    }
    if (not01) atomicOr(&s_not01, 1);
    if (notf)  atomicOr(&s_notf, 1);
    __syncthreads();
    if (threadIdx.x == 0)
        g_mask_mode = (!s_not01) ? 0 : (!s_notf ? 1 : 2);
}

// ---------------------------------------------------------------------------
// Kernel 4: masked softmax (sums the 4 score partials)
// ---------------------------------------------------------------------------
__global__ void softmax_kernel(const void* __restrict__ mask,
                               float* __restrict__ wout) {
    int b = blockIdx.x;
    int tid = threadIdx.x;
    int mode = g_mask_mode;
    __shared__ float red[256];

    float sv[8];
    float mx = -FLT_MAX;
    #pragma unroll
    for (int i = 0; i < 8; ++i) {
        int s = tid + i * 256;
        int idx = b * SS + s;
        float v = g_part[idx] + g_part[BB * SS + idx]
                + g_part[2 * BB * SS + idx] + g_part[3 * BB * SS + idx];
        bool m;
        if (mode == 0)      m = ((const int*)mask)[idx] != 0;
        else if (mode == 1) m = ((const float*)mask)[idx] != 0.f;
        else                m = ((const unsigned char*)mask)[idx] != 0;
        v = m ? -FLT_MAX : v;
        sv[i] = v;
        mx = fmaxf(mx, v);
    }
    red[tid] = mx; __syncthreads();
    for (int off = 128; off; off >>= 1) {
        if (tid < off) red[tid] = fmaxf(red[tid], red[tid + off]);
        __syncthreads();
    }
    mx = red[0];
    __syncthreads();

    float sum = 0.f;
    #pragma unroll
    for (int i = 0; i < 8; ++i) {
        float e = expf(sv[i] - mx);
        sv[i] = e;
        sum += e;
    }
    red[tid] = sum; __syncthreads();
    for (int off = 128; off; off >>= 1) {
        if (tid < off) red[tid] += red[tid + off];
        __syncthreads();
    }
    float inv = 1.f / red[0];
    #pragma unroll
    for (int i = 0; i < 8; ++i)
        wout[b * SS + tid + i * 256] = sv[i] * inv;
}

// ---------------------------------------------------------------------------
// Kernel 5: context[b,e] = sum_s w[b,s] * enc[b,s,e]
// ---------------------------------------------------------------------------
__global__ void context_kernel(const float* __restrict__ enc,
                               const float* __restrict__ w,
                               float* __restrict__ out) {
    int b = blockIdx.x;
    int e = blockIdx.y * 256 + threadIdx.x;
    const float* ep = enc + (size_t)b * SS * ED + e;
    const float* wp = w + b * SS;
    float acc = 0.f;
    for (int s = 0; s < SS; s += 16) {
        #pragma unroll
        for (int u = 0; u < 16; ++u)
            acc += wp[s + u] * ep[(size_t)(s + u) * ED];
    }
    out[(size_t)b * ED + e] = acc;
}

// ---------------------------------------------------------------------------
extern "C" void kernel_launch(void* const* d_in, const int* in_sizes, int n_in,
                              void* d_out, int out_size) {
    const float* decoder_hidden  = (const float*)d_in[0];
    const float* encoder_outputs = (const float*)d_in[1];
    const void*  mask            = d_in[2];
    const float* W_enc           = (const float*)d_in[3];
    const float* W_dec           = (const float*)d_in[4];
    const float* W_energy        = (const float*)d_in[5];

    float* out_context = (float*)d_out;
    float* out_weights = (float*)d_out + (size_t)BB * ED;

    static bool attr_set = false;
    const int dyn_bytes = NSTAGE * STAGE_FLOATS * 4;   // 147456
    if (!attr_set) {
        cudaFuncSetAttribute(score_mma_kernel,
                             cudaFuncAttributeMaxDynamicSharedMemorySize, dyn_bytes);
        attr_set = true;
    }

    decfeat_kernel<<<dim3(BB, AD / 8), 256>>>(decoder_hidden, W_dec);
    score_mma_kernel<<<dim3(4 * BB, SS / 128), 256, dyn_bytes>>>(
        encoder_outputs, W_enc, W_energy);
    mask_detect_kernel<<<1, 256>>>((const unsigned int*)mask);
    softmax_kernel<<<BB, 256>>>(mask, out_weights);
    context_kernel<<<dim3(BB, ED / 256), 256>>>(encoder_outputs, out_weights, out_context);
}

// round 13
// speedup vs baseline: 2.4083x; 2.4083x over previous
#include <cuda_runtime.h>
#include <cuda_fp16.h>
#include <math.h>
#include <float.h>
#include <stdint.h>

#define BB 64
#define SS 2048
#define ED 1024
#define AD 512

// Scratch (allocation-free rule: __device__ globals)
__device__ __half g_xh[(size_t)BB * SS * ED];   // 256MB fp16 X
__device__ __half g_wh[AD * ED];                // 1MB fp16 W_enc
__device__ float g_dec_feat[BB * AD];           // [B, AD]
__device__ float g_part[4 * BB * SS];           // [nc][B, S] score partials
__device__ int   g_mask_mode;                   // 0=int32, 1=float32, 2=uint8

__device__ __forceinline__ uint32_t smem_u32(const void* p) {
    uint32_t a;
    asm("{ .reg .u64 t; cvta.to.shared.u64 t, %1; cvt.u32.u64 %0, t; }"
        : "=r"(a) : "l"(p));
    return a;
}
__device__ __forceinline__ uint32_t swz(uint32_t off) {
    return off ^ ((off >> 3) & 0x70);
}
#define LDSM_X4(r0, r1, r2, r3, addr) \
    asm volatile("ldmatrix.sync.aligned.m8n8.x4.shared.b16 {%0,%1,%2,%3}, [%4];" \
        : "=r"(r0), "=r"(r1), "=r"(r2), "=r"(r3) : "r"(addr))

// ---------------------------------------------------------------------------
// Kernel 0a/0b: fp32 -> fp16 conversion (16 floats per thread)
// ---------------------------------------------------------------------------
__global__ void cvt_kernel(const float4* __restrict__ src, __half* __restrict__ dst) {
    size_t t = (size_t)blockIdx.x * blockDim.x + threadIdx.x;
    const float4* s = src + t * 4;
    float4 v0 = s[0], v1 = s[1], v2 = s[2], v3 = s[3];
    __half2 h[8];
    h[0] = __floats2half2_rn(v0.x, v0.y); h[1] = __floats2half2_rn(v0.z, v0.w);
    h[2] = __floats2half2_rn(v1.x, v1.y); h[3] = __floats2half2_rn(v1.z, v1.w);
    h[4] = __floats2half2_rn(v2.x, v2.y); h[5] = __floats2half2_rn(v2.z, v2.w);
    h[6] = __floats2half2_rn(v3.x, v3.y); h[7] = __floats2half2_rn(v3.z, v3.w);
    uint4 o0, o1;
    o0.x = *(uint32_t*)&h[0]; o0.y = *(uint32_t*)&h[1];
    o0.z = *(uint32_t*)&h[2]; o0.w = *(uint32_t*)&h[3];
    o1.x = *(uint32_t*)&h[4]; o1.y = *(uint32_t*)&h[5];
    o1.z = *(uint32_t*)&h[6]; o1.w = *(uint32_t*)&h[7];
    uint4* d = (uint4*)(dst + t * 16);
    d[0] = o0; d[1] = o1;
}

// ---------------------------------------------------------------------------
// Kernel 1: dec_feat[b][a] = dot(decoder_hidden[b], W_dec[a])  (fp32)
// ---------------------------------------------------------------------------
__global__ void decfeat_kernel(const float* __restrict__ dh,
                               const float* __restrict__ Wdec) {
    int b = blockIdx.x;
    __shared__ float s_dh[ED];
    for (int i = threadIdx.x; i < ED; i += 256) s_dh[i] = dh[b * ED + i];
    __syncthreads();
    int warp = threadIdx.x >> 5;
    int lane = threadIdx.x & 31;
    int a = blockIdx.y * 8 + warp;
    const float* wr = Wdec + (size_t)a * ED;
    float acc = 0.f;
    #pragma unroll 8
    for (int k = lane; k < ED; k += 32) acc += s_dh[k] * wr[k];
    #pragma unroll
    for (int off = 16; off; off >>= 1) acc += __shfl_down_sync(0xffffffffu, acc, off);
    if (lane == 0) g_dec_feat[b * AD + a] = acc;
}

// ---------------------------------------------------------------------------
// Kernel 2: fp16 m16n8k16 fused score kernel, ldmatrix fragments.
// Per CTA: 128 s-rows x 128 a-cols, K=1024, BK=64 (128B fp16 rows, SW128).
// partial[nc][b,s] = sum_{a in chunk} We[a] * tanh(X.Wenc^T + dec)
// ---------------------------------------------------------------------------
#define BKH 64
#define NKH (ED / BKH)           // 16
#define NSTAGE 4
#define STAGE_BYTES 32768        // X 128x128B + W 128x128B

__global__ void __launch_bounds__(256, 1)
score_mma_kernel(const __half* __restrict__ Xh,   // [B*S, ED]
                 const __half* __restrict__ Wh,   // [AD, ED]
                 const float* __restrict__ Wen)   // [AD]
{
    extern __shared__ char smem[];
    __shared__ float s_dec[128];
    __shared__ float s_we[128];
    __shared__ float s_red[2][128];

    int tid  = threadIdx.x;
    int wid  = tid >> 5;
    int lane = tid & 31;
    int g    = lane >> 2;
    int tig  = lane & 3;
    int warpm = wid & 3;       // 0..3
    int warpn = wid >> 2;      // 0..1

    int nc = blockIdx.x & 3;
    int b  = blockIdx.x >> 2;
    int s0 = blockIdx.y * 128;

    const __half* Xblk = Xh + (size_t)(b * SS + s0) * ED;
    const __half* Wblk = Wh + (size_t)(nc * 128) * ED;

    for (int i = tid; i < 128; i += 256) {
        s_dec[i] = g_dec_feat[b * AD + nc * 128 + i];
        s_we[i]  = Wen[nc * 128 + i];
    }

    uint32_t sm0 = smem_u32(smem);

    // cp.async: each thread owns 8 16B granules per stage
    int ld_row = (tid >> 3) & 127;   // row within region (from c = tid + i*256)
    auto issue_stage = [&](int p, int kc) {
        uint32_t base = sm0 + (uint32_t)(p * STAGE_BYTES);
        #pragma unroll
        for (int i = 0; i < 8; ++i) {
            int c = tid + i * 256;                 // 0..2047
            int row = (c >> 3) & 127;
            int q = c & 7;
            uint32_t off = swz((uint32_t)(row * 128 + q * 16));
            const __half* src;
            uint32_t dst;
            if (c < 1024) {
                src = Xblk + (size_t)row * ED + kc * BKH + q * 8;
                dst = base + off;
            } else {
                src = Wblk + (size_t)row * ED + kc * BKH + q * 8;
                dst = base + 16384u + off;
            }
            asm volatile("cp.async.cg.shared.global [%0], [%1], 16;"
                         :: "r"(dst), "l"(src));
        }
        asm volatile("cp.async.commit_group;" ::: "memory");
    };
    (void)ld_row;

    // ldmatrix per-lane address precompute
    // A (x4 per mf): groups: m-lo/k-lo, m-hi/k-lo, m-lo/k-hi, m-hi/k-hi
    uint32_t aBase[2], aXor[2];
    #pragma unroll
    for (int mf = 0; mf < 2; ++mf) {
        int r = warpm * 32 + mf * 16 + (lane & 15);
        aBase[mf] = (uint32_t)(r * 128);
        aXor[mf]  = (uint32_t)((r & 7) << 4);
    }
    uint32_t aSel = (uint32_t)((lane >> 4) * 16);
    // B (x4 per j, covers nf=2j,2j+1): groups: n-lo/k-lo, n-lo/k-hi, n-hi/k-lo, n-hi/k-hi
    uint32_t bBase[4], bXor[4];
    #pragma unroll
    for (int j = 0; j < 4; ++j) {
        int r = warpn * 64 + j * 16 + (lane & 7) + ((lane >> 4) & 1) * 8;
        bBase[j] = 16384u + (uint32_t)(r * 128);
        bXor[j]  = (uint32_t)((r & 7) << 4);
    }
    uint32_t bSel = (uint32_t)(((lane >> 3) & 1) * 16);

    // prologue: stages 0..2
    issue_stage(0, 0);
    issue_stage(1, 1);
    issue_stage(2, 2);

    float acc[2][8][4];
    #pragma unroll
    for (int mf = 0; mf < 2; ++mf)
        #pragma unroll
        for (int nf = 0; nf < 8; ++nf)
            #pragma unroll
            for (int r = 0; r < 4; ++r) acc[mf][nf][r] = 0.f;

    for (int kt = 0; kt < NKH; ++kt) {
        int p = kt & (NSTAGE - 1);
        asm volatile("cp.async.wait_group %0;" :: "n"(NSTAGE - 2) : "memory");
        __syncthreads();

        uint32_t stg = sm0 + (uint32_t)(p * STAGE_BYTES);

        #pragma unroll
        for (int ks = 0; ks < 4; ++ks) {
            uint32_t kof = (uint32_t)(ks * 32);
            uint32_t A[2][4];
            #pragma unroll
            for (int mf = 0; mf < 2; ++mf) {
                uint32_t addr = stg + aBase[mf] + ((kof + aSel) ^ aXor[mf]);
                LDSM_X4(A[mf][0], A[mf][1], A[mf][2], A[mf][3], addr);
            }
            uint32_t Bm[4][4];
            #pragma unroll
            for (int j = 0; j < 4; ++j) {
                uint32_t addr = stg + bBase[j] + ((kof + bSel) ^ bXor[j]);
                LDSM_X4(Bm[j][0], Bm[j][1], Bm[j][2], Bm[j][3], addr);
            }
            #pragma unroll
            for (int mf = 0; mf < 2; ++mf)
                #pragma unroll
                for (int nf = 0; nf < 8; ++nf) {
                    float* c = acc[mf][nf];
                    uint32_t b0 = Bm[nf >> 1][(nf & 1) * 2];
                    uint32_t b1 = Bm[nf >> 1][(nf & 1) * 2 + 1];
                    asm volatile(
                        "mma.sync.aligned.m16n8k16.row.col.f32.f16.f16.f32 "
                        "{%0,%1,%2,%3}, {%4,%5,%6,%7}, {%8,%9}, {%0,%1,%2,%3};"
                        : "+f"(c[0]), "+f"(c[1]), "+f"(c[2]), "+f"(c[3])
                        : "r"(A[mf][0]), "r"(A[mf][1]), "r"(A[mf][2]), "r"(A[mf][3]),
                          "r"(b0), "r"(b1));
                }
        }
        __syncthreads();
        if (kt + NSTAGE - 1 < NKH)
            issue_stage((kt + NSTAGE - 1) & (NSTAGE - 1), kt + NSTAGE - 1);
    }

    // ---- epilogue: tanh + We reduction (C layout: cols 2tig,2tig+1; rows g,g+8) ----
    #pragma unroll
    for (int mf = 0; mf < 2; ++mf) {
        float sum0 = 0.f, sum1 = 0.f;
        #pragma unroll
        for (int nf = 0; nf < 8; ++nf) {
            int cA = warpn * 64 + nf * 8 + 2 * tig;
            int cB = cA + 1;
            sum0 += s_we[cA] * tanhf(acc[mf][nf][0] + s_dec[cA])
                  + s_we[cB] * tanhf(acc[mf][nf][1] + s_dec[cB]);
            sum1 += s_we[cA] * tanhf(acc[mf][nf][2] + s_dec[cA])
                  + s_we[cB] * tanhf(acc[mf][nf][3] + s_dec[cB]);
        }
        sum0 += __shfl_xor_sync(0xffffffffu, sum0, 1);
        sum0 += __shfl_xor_sync(0xffffffffu, sum0, 2);
        sum1 += __shfl_xor_sync(0xffffffffu, sum1, 1);
        sum1 += __shfl_xor_sync(0xffffffffu, sum1, 2);
        if (tig == 0) {
            int r0 = warpm * 32 + mf * 16 + g;
            s_red[warpn][r0]     = sum0;
            s_red[warpn][r0 + 8] = sum1;
        }
    }
    __syncthreads();
    if (tid < 128)
        g_part[nc * BB * SS + b * SS + s0 + tid] = s_red[0][tid] + s_red[1][tid];
}

// ---------------------------------------------------------------------------
// Kernel 3: mask dtype detect
// ---------------------------------------------------------------------------
__global__ void mask_detect_kernel(const unsigned int* __restrict__ mw) {
    __shared__ int s_not01, s_notf;
    if (threadIdx.x == 0) { s_not01 = 0; s_notf = 0; }
    __syncthreads();
    int not01 = 0, notf = 0;
    for (int i = threadIdx.x; i < 32768; i += blockDim.x) {
        unsigned int w = mw[i];
        if (w > 1u) not01 = 1;
        if (w != 0u && w != 0x3F800000u) notf = 1;
    }
    if (not01) atomicOr(&s_not01, 1);
    if (notf)  atomicOr(&s_notf, 1);
    __syncthreads();
    if (threadIdx.x == 0)
        g_mask_mode = (!s_not01) ? 0 : (!s_notf ? 1 : 2);
}

// ---------------------------------------------------------------------------
// Kernel 4: masked softmax (sums the 4 score partials)
// ---------------------------------------------------------------------------
__global__ void softmax_kernel(const void* __restrict__ mask,
                               float* __restrict__ wout) {
    int b = blockIdx.x;
    int tid = threadIdx.x;
    int mode = g_mask_mode;
    __shared__ float red[256];

    float sv[8];
    float mx = -FLT_MAX;
    #pragma unroll
    for (int i = 0; i < 8; ++i) {
        int s = tid + i * 256;
        int idx = b * SS + s;
        float v = g_part[idx] + g_part[BB * SS + idx]
                + g_part[2 * BB * SS + idx] + g_part[3 * BB * SS + idx];
        bool m;
        if (mode == 0)      m = ((const int*)mask)[idx] != 0;
        else if (mode == 1) m = ((const float*)mask)[idx] != 0.f;
        else                m = ((const unsigned char*)mask)[idx] != 0;
        v = m ? -FLT_MAX : v;
        sv[i] = v;
        mx = fmaxf(mx, v);
    }
    red[tid] = mx; __syncthreads();
    for (int off = 128; off; off >>= 1) {
        if (tid < off) red[tid] = fmaxf(red[tid], red[tid + off]);
        __syncthreads();
    }
    mx = red[0];
    __syncthreads();

    float sum = 0.f;
    #pragma unroll
    for (int i = 0; i < 8; ++i) {
        float e = expf(sv[i] - mx);
        sv[i] = e;
        sum += e;
    }
    red[tid] = sum; __syncthreads();
    for (int off = 128; off; off >>= 1) {
        if (tid < off) red[tid] += red[tid + off];
        __syncthreads();
    }
    float inv = 1.f / red[0];
    #pragma unroll
    for (int i = 0; i < 8; ++i)
        wout[b * SS + tid + i * 256] = sv[i] * inv;
}

// ---------------------------------------------------------------------------
// Kernel 5: context[b,e] = sum_s w[b,s] * enc[b,s,e]
// ---------------------------------------------------------------------------
__global__ void context_kernel(const float* __restrict__ enc,
                               const float* __restrict__ w,
                               float* __restrict__ out) {
    int b = blockIdx.x;
    int e = blockIdx.y * 256 + threadIdx.x;
    const float* ep = enc + (size_t)b * SS * ED + e;
    const float* wp = w + b * SS;
    float acc = 0.f;
    for (int s = 0; s < SS; s += 16) {
        #pragma unroll
        for (int u = 0; u < 16; ++u)
            acc += wp[s + u] * ep[(size_t)(s + u) * ED];
    }
    out[(size_t)b * ED + e] = acc;
}

// ---------------------------------------------------------------------------
extern "C" void kernel_launch(void* const* d_in, const int* in_sizes, int n_in,
                              void* d_out, int out_size) {
    const float* decoder_hidden  = (const float*)d_in[0];
    const float* encoder_outputs = (const float*)d_in[1];
    const void*  mask            = d_in[2];
    const float* W_enc           = (const float*)d_in[3];
    const float* W_dec           = (const float*)d_in[4];
    const float* W_energy        = (const float*)d_in[5];

    float* out_context = (float*)d_out;
    float* out_weights = (float*)d_out + (size_t)BB * ED;

    __half *d_xh, *d_wh;
    cudaGetSymbolAddress((void**)&d_xh, g_xh);
    cudaGetSymbolAddress((void**)&d_wh, g_wh);

    static bool attr_set = false;
    const int dyn_bytes = NSTAGE * STAGE_BYTES;   // 131072
    if (!attr_set) {
        cudaFuncSetAttribute(score_mma_kernel,
                             cudaFuncAttributeMaxDynamicSharedMemorySize, dyn_bytes);
        attr_set = true;
    }

    // fp32 -> fp16 conversion: X (134217728 floats / 16 per thread)
    cvt_kernel<<<32768, 256>>>((const float4*)encoder_outputs, d_xh);
    // W_enc: 524288 floats / 16 per thread = 32768 threads
    cvt_kernel<<<128, 256>>>((const float4*)W_enc, d_wh);

    decfeat_kernel<<<dim3(BB, AD / 8), 256>>>(decoder_hidden, W_dec);
    score_mma_kernel<<<dim3(4 * BB, SS / 128), 256, dyn_bytes>>>(
        d_xh, d_wh, W_energy);
    mask_detect_kernel<<<1, 256>>>((const unsigned int*)mask);
    softmax_kernel<<<BB, 256>>>(mask, out_weights);
    context_kernel<<<dim3(BB, ED / 256), 256>>>(encoder_outputs, out_weights, out_context);
}

// round 14
// speedup vs baseline: 2.8593x; 1.1873x over previous
#include <cuda_runtime.h>
#include <cuda_fp16.h>
#include <math.h>
#include <float.h>
#include <stdint.h>

#define BB 64
#define SS 2048
#define ED 1024
#define AD 512

// Scratch (allocation-free rule: __device__ globals)
__device__ __half g_xh[(size_t)BB * SS * ED];   // 256MB fp16 X
__device__ __half g_wh[AD * ED];                // 1MB fp16 W_enc
__device__ float g_dec_feat[BB * AD];           // [B, AD]
__device__ float g_part[4 * BB * SS];           // [nc][B, S] score partials
__device__ int   g_mask_mode;                   // 0=int32, 1=float32, 2=uint8

__device__ __forceinline__ uint32_t smem_u32(const void* p) {
    uint32_t a;
    asm("{ .reg .u64 t; cvta.to.shared.u64 t, %1; cvt.u32.u64 %0, t; }"
        : "=r"(a) : "l"(p));
    return a;
}
__device__ __forceinline__ uint32_t swz(uint32_t off) {
    return off ^ ((off >> 3) & 0x70);
}
#define LDSM_X4(r0, r1, r2, r3, addr) \
    asm volatile("ldmatrix.sync.aligned.m8n8.x4.shared.b16 {%0,%1,%2,%3}, [%4];" \
        : "=r"(r0), "=r"(r1), "=r"(r2), "=r"(r3) : "r"(addr))

// ---------------------------------------------------------------------------
// Kernel 0: fp32 -> fp16 conversion (16 floats per thread)
// ---------------------------------------------------------------------------
__global__ void cvt_kernel(const float4* __restrict__ src, __half* __restrict__ dst) {
    size_t t = (size_t)blockIdx.x * blockDim.x + threadIdx.x;
    const float4* s = src + t * 4;
    float4 v0 = s[0], v1 = s[1], v2 = s[2], v3 = s[3];
    __half2 h[8];
    h[0] = __floats2half2_rn(v0.x, v0.y); h[1] = __floats2half2_rn(v0.z, v0.w);
    h[2] = __floats2half2_rn(v1.x, v1.y); h[3] = __floats2half2_rn(v1.z, v1.w);
    h[4] = __floats2half2_rn(v2.x, v2.y); h[5] = __floats2half2_rn(v2.z, v2.w);
    h[6] = __floats2half2_rn(v3.x, v3.y); h[7] = __floats2half2_rn(v3.z, v3.w);
    uint4 o0, o1;
    o0.x = *(uint32_t*)&h[0]; o0.y = *(uint32_t*)&h[1];
    o0.z = *(uint32_t*)&h[2]; o0.w = *(uint32_t*)&h[3];
    o1.x = *(uint32_t*)&h[4]; o1.y = *(uint32_t*)&h[5];
    o1.z = *(uint32_t*)&h[6]; o1.w = *(uint32_t*)&h[7];
    uint4* d = (uint4*)(dst + t * 16);
    d[0] = o0; d[1] = o1;
}

// ---------------------------------------------------------------------------
// Kernel 1: dec_feat[b][a] = dot(decoder_hidden[b], W_dec[a])  (fp32)
// ---------------------------------------------------------------------------
__global__ void decfeat_kernel(const float* __restrict__ dh,
                               const float* __restrict__ Wdec) {
    int b = blockIdx.x;
    __shared__ float s_dh[ED];
    for (int i = threadIdx.x; i < ED; i += 256) s_dh[i] = dh[b * ED + i];
    __syncthreads();
    int warp = threadIdx.x >> 5;
    int lane = threadIdx.x & 31;
    int a = blockIdx.y * 8 + warp;
    const float* wr = Wdec + (size_t)a * ED;
    float acc = 0.f;
    #pragma unroll 8
    for (int k = lane; k < ED; k += 32) acc += s_dh[k] * wr[k];
    #pragma unroll
    for (int off = 16; off; off >>= 1) acc += __shfl_down_sync(0xffffffffu, acc, off);
    if (lane == 0) g_dec_feat[b * AD + a] = acc;
}

// ---------------------------------------------------------------------------
// Kernel 2: fp16 m16n8k16 fused score kernel, ldmatrix fragments.
// Per CTA: 128 s-rows x 128 a-cols, K=1024, BK=64 (128B fp16 rows, SW128).
// NSTAGE=3 (96KB) -> 2 CTAs/SM; ONE __syncthreads per k-iteration.
// partial[nc][b,s] = sum_{a in chunk} We[a] * tanh(X.Wenc^T + dec)
// ---------------------------------------------------------------------------
#define BKH 64
#define NKH (ED / BKH)           // 16
#define NSTAGE 3
#define STAGE_BYTES 32768        // X 128x128B + W 128x128B

__global__ void __launch_bounds__(256, 2)
score_mma_kernel(const __half* __restrict__ Xh,   // [B*S, ED]
                 const __half* __restrict__ Wh,   // [AD, ED]
                 const float* __restrict__ Wen)   // [AD]
{
    extern __shared__ char smem[];
    __shared__ float s_dec[128];
    __shared__ float s_we[128];
    __shared__ float s_red[2][128];

    int tid  = threadIdx.x;
    int wid  = tid >> 5;
    int lane = tid & 31;
    int g    = lane >> 2;
    int tig  = lane & 3;
    int warpm = wid & 3;       // 0..3
    int warpn = wid >> 2;      // 0..1

    int nc = blockIdx.x & 3;
    int b  = blockIdx.x >> 2;
    int s0 = blockIdx.y * 128;

    const __half* Xblk = Xh + (size_t)(b * SS + s0) * ED;
    const __half* Wblk = Wh + (size_t)(nc * 128) * ED;

    for (int i = tid; i < 128; i += 256) {
        s_dec[i] = g_dec_feat[b * AD + nc * 128 + i];
        s_we[i]  = Wen[nc * 128 + i];
    }

    uint32_t sm0 = smem_u32(smem);

    // cp.async: each thread owns 8 16B granules per stage
    auto issue_stage = [&](int p, int kc) {
        uint32_t base = sm0 + (uint32_t)(p * STAGE_BYTES);
        #pragma unroll
        for (int i = 0; i < 8; ++i) {
            int c = tid + i * 256;                 // 0..2047
            int row = (c >> 3) & 127;
            int q = c & 7;
            uint32_t off = swz((uint32_t)(row * 128 + q * 16));
            const __half* src;
            uint32_t dst;
            if (c < 1024) {
                src = Xblk + (size_t)row * ED + kc * BKH + q * 8;
                dst = base + off;
            } else {
                src = Wblk + (size_t)row * ED + kc * BKH + q * 8;
                dst = base + 16384u + off;
            }
            asm volatile("cp.async.cg.shared.global [%0], [%1], 16;"
                         :: "r"(dst), "l"(src));
        }
        asm volatile("cp.async.commit_group;" ::: "memory");
    };

    // ldmatrix per-lane address precompute
    uint32_t aBase[2], aXor[2];
    #pragma unroll
    for (int mf = 0; mf < 2; ++mf) {
        int r = warpm * 32 + mf * 16 + (lane & 15);
        aBase[mf] = (uint32_t)(r * 128);
        aXor[mf]  = (uint32_t)((r & 7) << 4);
    }
    uint32_t aSel = (uint32_t)((lane >> 4) * 16);
    uint32_t bBase[4], bXor[4];
    #pragma unroll
    for (int j = 0; j < 4; ++j) {
        int r = warpn * 64 + j * 16 + (lane & 7) + ((lane >> 4) & 1) * 8;
        bBase[j] = 16384u + (uint32_t)(r * 128);
        bXor[j]  = (uint32_t)((r & 7) << 4);
    }
    uint32_t bSel = (uint32_t)(((lane >> 3) & 1) * 16);

    // prologue: stages 0,1
    issue_stage(0, 0);
    issue_stage(1, 1);

    float acc[2][8][4];
    #pragma unroll
    for (int mf = 0; mf < 2; ++mf)
        #pragma unroll
        for (int nf = 0; nf < 8; ++nf)
            #pragma unroll
            for (int r = 0; r < 4; ++r) acc[mf][nf][r] = 0.f;

    int p = 0;          // stage being consumed
    int pw = 2;         // stage to fill next
    for (int kt = 0; kt < NKH; ++kt) {
        asm volatile("cp.async.wait_group %0;" :: "n"(NSTAGE - 2) : "memory");
        __syncthreads();   // stage p visible to all; all warps done with stage pw

        if (kt + NSTAGE - 1 < NKH)
            issue_stage(pw, kt + NSTAGE - 1);

        uint32_t stg = sm0 + (uint32_t)(p * STAGE_BYTES);

        #pragma unroll
        for (int ks = 0; ks < 4; ++ks) {
            uint32_t kof = (uint32_t)(ks * 32);
            uint32_t A[2][4];
            #pragma unroll
            for (int mf = 0; mf < 2; ++mf) {
                uint32_t addr = stg + aBase[mf] + ((kof + aSel) ^ aXor[mf]);
                LDSM_X4(A[mf][0], A[mf][1], A[mf][2], A[mf][3], addr);
            }
            uint32_t Bm[4][4];
            #pragma unroll
            for (int j = 0; j < 4; ++j) {
                uint32_t addr = stg + bBase[j] + ((kof + bSel) ^ bXor[j]);
                LDSM_X4(Bm[j][0], Bm[j][1], Bm[j][2], Bm[j][3], addr);
            }
            #pragma unroll
            for (int mf = 0; mf < 2; ++mf)
                #pragma unroll
                for (int nf = 0; nf < 8; ++nf) {
                    float* c = acc[mf][nf];
                    uint32_t b0 = Bm[nf >> 1][(nf & 1) * 2];
                    uint32_t b1 = Bm[nf >> 1][(nf & 1) * 2 + 1];
                    asm volatile(
                        "mma.sync.aligned.m16n8k16.row.col.f32.f16.f16.f32 "
                        "{%0,%1,%2,%3}, {%4,%5,%6,%7}, {%8,%9}, {%0,%1,%2,%3};"
                        : "+f"(c[0]), "+f"(c[1]), "+f"(c[2]), "+f"(c[3])
                        : "r"(A[mf][0]), "r"(A[mf][1]), "r"(A[mf][2]), "r"(A[mf][3]),
                          "r"(b0), "r"(b1));
                }
        }
        pw = p;
        p = (p + 1 == NSTAGE) ? 0 : p + 1;
    }

    // ---- epilogue: tanh + We reduction (C layout: cols 2tig,2tig+1; rows g,g+8) ----
    #pragma unroll
    for (int mf = 0; mf < 2; ++mf) {
        float sum0 = 0.f, sum1 = 0.f;
        #pragma unroll
        for (int nf = 0; nf < 8; ++nf) {
            int cA = warpn * 64 + nf * 8 + 2 * tig;
            int cB = cA + 1;
            sum0 += s_we[cA] * tanhf(acc[mf][nf][0] + s_dec[cA])
                  + s_we[cB] * tanhf(acc[mf][nf][1] + s_dec[cB]);
            sum1 += s_we[cA] * tanhf(acc[mf][nf][2] + s_dec[cA])
                  + s_we[cB] * tanhf(acc[mf][nf][3] + s_dec[cB]);
        }
        sum0 += __shfl_xor_sync(0xffffffffu, sum0, 1);
        sum0 += __shfl_xor_sync(0xffffffffu, sum0, 2);
        sum1 += __shfl_xor_sync(0xffffffffu, sum1, 1);
        sum1 += __shfl_xor_sync(0xffffffffu, sum1, 2);
        if (tig == 0) {
            int r0 = warpm * 32 + mf * 16 + g;
            s_red[warpn][r0]     = sum0;
            s_red[warpn][r0 + 8] = sum1;
        }
    }
    __syncthreads();
    if (tid < 128)
        g_part[nc * BB * SS + b * SS + s0 + tid] = s_red[0][tid] + s_red[1][tid];
}

// ---------------------------------------------------------------------------
// Kernel 3: mask dtype detect
// ---------------------------------------------------------------------------
__global__ void mask_detect_kernel(const unsigned int* __restrict__ mw) {
    __shared__ int s_not01, s_notf;
    if (threadIdx.x == 0) { s_not01 = 0; s_notf = 0; }
    __syncthreads();
    int not01 = 0, notf = 0;
    for (int i = threadIdx.x; i < 32768; i += blockDim.x) {
        unsigned int w = mw[i];
        if (w > 1u) not01 = 1;
        if (w != 0u && w != 0x3F800000u) notf = 1;
    }
    if (not01) atomicOr(&s_not01, 1);
    if (notf)  atomicOr(&s_notf, 1);
    __syncthreads();
    if (threadIdx.x == 0)
        g_mask_mode = (!s_not01) ? 0 : (!s_notf ? 1 : 2);
}

// ---------------------------------------------------------------------------
// Kernel 4: masked softmax (sums the 4 score partials)
// ---------------------------------------------------------------------------
__global__ void softmax_kernel(const void* __restrict__ mask,
                               float* __restrict__ wout) {
    int b = blockIdx.x;
    int tid = threadIdx.x;
    int mode = g_mask_mode;
    __shared__ float red[256];

    float sv[8];
    float mx = -FLT_MAX;
    #pragma unroll
    for (int i = 0; i < 8; ++i) {
        int s = tid + i * 256;
        int idx = b * SS + s;
        float v = g_part[idx] + g_part[BB * SS + idx]
                + g_part[2 * BB * SS + idx] + g_part[3 * BB * SS + idx];
        bool m;
        if (mode == 0)      m = ((const int*)mask)[idx] != 0;
        else if (mode == 1) m = ((const float*)mask)[idx] != 0.f;
        else                m = ((const unsigned char*)mask)[idx] != 0;
        v = m ? -FLT_MAX : v;
        sv[i] = v;
        mx = fmaxf(mx, v);
    }
    red[tid] = mx; __syncthreads();
    for (int off = 128; off; off >>= 1) {
        if (tid < off) red[tid] = fmaxf(red[tid], red[tid + off]);
        __syncthreads();
    }
    mx = red[0];
    __syncthreads();

    float sum = 0.f;
    #pragma unroll
    for (int i = 0; i < 8; ++i) {
        float e = expf(sv[i] - mx);
        sv[i] = e;
        sum += e;
    }
    red[tid] = sum; __syncthreads();
    for (int off = 128; off; off >>= 1) {
        if (tid < off) red[tid] += red[tid + off];
        __syncthreads();
    }
    float inv = 1.f / red[0];
    #pragma unroll
    for (int i = 0; i < 8; ++i)
        wout[b * SS + tid + i * 256] = sv[i] * inv;
}

// ---------------------------------------------------------------------------
// Kernel 5: context[b,e] = sum_s w[b,s] * xh[b,s,e]  (fp16 X, halves traffic)
// ---------------------------------------------------------------------------
__global__ void context_kernel(const __half* __restrict__ xh,
                               const float* __restrict__ w,
                               float* __restrict__ out) {
    int b = blockIdx.x;
    int e = blockIdx.y * 256 + threadIdx.x;
    const __half* ep = xh + (size_t)b * SS * ED + e;
    const float* wp = w + b * SS;
    float acc = 0.f;
    for (int s = 0; s < SS; s += 16) {
        #pragma unroll
        for (int u = 0; u < 16; ++u)
            acc += wp[s + u] * __half2float(ep[(size_t)(s + u) * ED]);
    }
    out[(size_t)b * ED + e] = acc;
}

// ---------------------------------------------------------------------------
extern "C" void kernel_launch(void* const* d_in, const int* in_sizes, int n_in,
                              void* d_out, int out_size) {
    const float* decoder_hidden  = (const float*)d_in[0];
    const float* encoder_outputs = (const float*)d_in[1];
    const void*  mask            = d_in[2];
    const float* W_enc           = (const float*)d_in[3];
    const float* W_dec           = (const float*)d_in[4];
    const float* W_energy        = (const float*)d_in[5];

    float* out_context = (float*)d_out;
    float* out_weights = (float*)d_out + (size_t)BB * ED;

    __half *d_xh, *d_wh;
    cudaGetSymbolAddress((void**)&d_xh, g_xh);
    cudaGetSymbolAddress((void**)&d_wh, g_wh);

    static bool attr_set = false;
    const int dyn_bytes = NSTAGE * STAGE_BYTES;   // 98304
    if (!attr_set) {
        cudaFuncSetAttribute(score_mma_kernel,
                             cudaFuncAttributeMaxDynamicSharedMemorySize, dyn_bytes);
        attr_set = true;
    }

    cvt_kernel<<<32768, 256>>>((const float4*)encoder_outputs, d_xh);
    cvt_kernel<<<128, 256>>>((const float4*)W_enc, d_wh);

    decfeat_kernel<<<dim3(BB, AD / 8), 256>>>(decoder_hidden, W_dec);
    score_mma_kernel<<<dim3(4 * BB, SS / 128), 256, dyn_bytes>>>(
        d_xh, d_wh, W_energy);
    mask_detect_kernel<<<1, 256>>>((const unsigned int*)mask);
    softmax_kernel<<<BB, 256>>>(mask, out_weights);
    context_kernel<<<dim3(BB, ED / 256), 256>>>(d_xh, out_weights, out_context);
}